// round 2
// baseline (speedup 1.0000x reference)
#include <cuda_runtime.h>
#include <cooperative_groups.h>
#include <math.h>

namespace cg = cooperative_groups;

// ---------------- Problem constants ----------------
#define BB    32
#define SS    512
#define EE    512
#define HH    256
#define H4    1024
#define H2    512
#define MM    (BB*SS)      // 16384
#define NSLOT 128
#define NINT  64

// ---------------- Scratch (device globals; no allocation allowed) ----------------
__device__ float g_pre[(size_t)MM*2048];     // input-proj output, both dirs (128MB)
__device__ float g_out0[(size_t)MM*H2];      // layer-0 output
__device__ float g_out1[(size_t)MM*H2];      // layer-1 output (encoder out)
__device__ float g_scores[(size_t)MM*H2];    // attention scores (B,512,512); reused as A_tmp
__device__ float g_slotctx[(size_t)MM*H2];   // slot context
__device__ float g_icl[BB*H2];
__device__ float g_wvsum[H2];
__device__ float g_bvsum[1];

// ---------------- Generic fp32 GEMM: C = A @ op(B) + bias ----------------
// TRANSB=true : B is (N,K) row-major -> C = A @ B^T
// TRANSB=false: B is (K,N) row-major -> C = A @ B
// GATHER=true : row m of A = gtab[gidx[m]*K + k]
// Tiles 128x128xBK16, 256 threads, 8x8 per thread. M%128==0, N%128==0, K%16==0.
template<bool TRANSB, bool GATHER>
__global__ void __launch_bounds__(256) gemm_kernel(
    const float* __restrict__ A, const float* __restrict__ Bm,
    const float* __restrict__ bias, float* __restrict__ C,
    int M, int N, int K,
    long sA, long sB, long sC,
    const int* __restrict__ gidx, const float* __restrict__ gtab)
{
    __shared__ float As[16][128];
    __shared__ float Bs[16][128];

    const int tid = threadIdx.x;
    const int tx = tid & 15, ty = tid >> 4;
    const int nbase = blockIdx.x * 128;
    const int mbase = blockIdx.y * 128;

    const float* Ab = GATHER ? gtab : (A + blockIdx.z * sA);
    const float* Bb = Bm + blockIdx.z * sB;
    float*       Cb = C  + blockIdx.z * sC;

    float acc[8][8];
#pragma unroll
    for (int i = 0; i < 8; ++i)
#pragma unroll
        for (int j = 0; j < 8; ++j) acc[i][j] = 0.f;

    // A load slots: 512 float4 per tile, 2 per thread
    const int rowA0 = tid >> 2;          // 0..63
    const int rowA1 = rowA0 + 64;        // 64..127
    const int kqA   = (tid & 3) * 4;     // 0,4,8,12
    long aoff0, aoff1;
    if (GATHER) {
        aoff0 = (long)gidx[mbase + rowA0] * K;
        aoff1 = (long)gidx[mbase + rowA1] * K;
    } else {
        aoff0 = (long)(mbase + rowA0) * K;
        aoff1 = (long)(mbase + rowA1) * K;
    }
    // B load slots
    long boff0 = 0, boff1 = 0; int kB0 = 0, kB1 = 0, n4 = 0;
    if (TRANSB) {
        boff0 = (long)(nbase + rowA0) * K;
        boff1 = (long)(nbase + rowA1) * K;
    } else {
        kB0 = tid >> 5;      // 0..7
        kB1 = kB0 + 8;       // 8..15
        n4  = tid & 31;      // 0..31
    }

    for (int kt = 0; kt < K; kt += 16) {
        float4 a0 = *(const float4*)(Ab + aoff0 + kt + kqA);
        float4 a1 = *(const float4*)(Ab + aoff1 + kt + kqA);
        As[kqA+0][rowA0] = a0.x; As[kqA+1][rowA0] = a0.y;
        As[kqA+2][rowA0] = a0.z; As[kqA+3][rowA0] = a0.w;
        As[kqA+0][rowA1] = a1.x; As[kqA+1][rowA1] = a1.y;
        As[kqA+2][rowA1] = a1.z; As[kqA+3][rowA1] = a1.w;

        if (TRANSB) {
            float4 b0 = *(const float4*)(Bb + boff0 + kt + kqA);
            float4 b1 = *(const float4*)(Bb + boff1 + kt + kqA);
            Bs[kqA+0][rowA0] = b0.x; Bs[kqA+1][rowA0] = b0.y;
            Bs[kqA+2][rowA0] = b0.z; Bs[kqA+3][rowA0] = b0.w;
            Bs[kqA+0][rowA1] = b1.x; Bs[kqA+1][rowA1] = b1.y;
            Bs[kqA+2][rowA1] = b1.z; Bs[kqA+3][rowA1] = b1.w;
        } else {
            float4 b0 = *(const float4*)(Bb + (long)(kt + kB0) * N + nbase + n4 * 4);
            float4 b1 = *(const float4*)(Bb + (long)(kt + kB1) * N + nbase + n4 * 4);
            *(float4*)&Bs[kB0][n4 * 4] = b0;
            *(float4*)&Bs[kB1][n4 * 4] = b1;
        }
        __syncthreads();

#pragma unroll
        for (int k = 0; k < 16; ++k) {
            float4 av0 = *(const float4*)&As[k][ty * 8];
            float4 av1 = *(const float4*)&As[k][ty * 8 + 4];
            float4 bv0 = *(const float4*)&Bs[k][tx * 8];
            float4 bv1 = *(const float4*)&Bs[k][tx * 8 + 4];
            float aR[8] = {av0.x, av0.y, av0.z, av0.w, av1.x, av1.y, av1.z, av1.w};
            float bR[8] = {bv0.x, bv0.y, bv0.z, bv0.w, bv1.x, bv1.y, bv1.z, bv1.w};
#pragma unroll
            for (int i = 0; i < 8; ++i)
#pragma unroll
                for (int j = 0; j < 8; ++j)
                    acc[i][j] += aR[i] * bR[j];
        }
        __syncthreads();
    }

    float bb[8];
#pragma unroll
    for (int j = 0; j < 8; ++j) bb[j] = bias ? bias[nbase + tx * 8 + j] : 0.f;

#pragma unroll
    for (int i = 0; i < 8; ++i) {
        long m = mbase + ty * 8 + i;
        float* crow = Cb + m * (long)N + nbase + tx * 8;
        float4 r0 = make_float4(acc[i][0] + bb[0], acc[i][1] + bb[1],
                                acc[i][2] + bb[2], acc[i][3] + bb[3]);
        float4 r1 = make_float4(acc[i][4] + bb[4], acc[i][5] + bb[5],
                                acc[i][6] + bb[6], acc[i][7] + bb[7]);
        *(float4*)crow       = r0;
        *(float4*)(crow + 4) = r1;
    }
}

// ---------------- BiLSTM recurrence (one layer; both dirs) ----------------
// grid = 128 blocks, clusters of 8. cluster id: dir = cid&1, batch group = cid>>1 (4 batches).
// CTA rank owns hidden j in [rank*32, rank*32+32) for all 4 gate types.
// Whh slice (128 rows x 256, pitch 260) resident in SMEM. h exchanged via DSMEM,
// one cluster.sync per step (double-buffered own-h slices).
__device__ __forceinline__ float sigm(float x) { return 1.f / (1.f + expf(-x)); }

#define WPITCH 260
#define LSTM_SMEM_FLOATS (128*WPITCH + 1024 + 256 + 512 + 128 + 128)

__global__ void __cluster_dims__(8, 1, 1) __launch_bounds__(128, 1)
lstm_kernel(const float* __restrict__ pre, const float* __restrict__ Whh,
            const float* __restrict__ bhh, float* __restrict__ out)
{
    extern __shared__ float sm[];
    float* sWhh  = sm;                       // [128][260]
    float* sH    = sm + 128 * WPITCH;        // [4][256]
    float* sHown = sH + 1024;                // [2][128]  (parity, b*32+jj)
    float* sG    = sHown + 256;              // [128][4]
    float* sBhh  = sG + 512;                 // [128]
    float* sC    = sBhh + 128;               // [128]

    cg::cluster_group cluster = cg::this_cluster();
    const int rank = cluster.block_rank();
    const int cid  = blockIdx.x >> 3;
    const int dir  = cid & 1;
    const int b0   = (cid >> 1) * 4;
    const int tid  = threadIdx.x;

    const int type = tid >> 5, jj = tid & 31;
    const int grow = type * 256 + rank * 32 + jj;   // this thread's gate row

    // load Whh slice (coalesced over k)
    for (int i = tid; i < 128 * 256; i += 128) {
        int r = i >> 8, k = i & 255;
        int gr = ((r >> 5) * 256) + rank * 32 + (r & 31);
        sWhh[r * WPITCH + k] = Whh[(long)(dir * 1024 + gr) * 256 + k];
    }
    sBhh[tid] = bhh[dir * 1024 + grow];
    for (int i = tid; i < 1024; i += 128) sH[i] = 0.f;
    for (int i = tid; i < 256;  i += 128) sHown[i] = 0.f;
    sC[tid] = 0.f;
    __syncthreads();

    const float* preBase = pre + dir * 1024 + grow;
    int par = 0;

    for (int t = 0; t < 512; ++t) {
        const int te = dir ? (511 - t) : t;

        float pv0 = preBase[(long)((b0 + 0) * 512 + te) * 2048];
        float pv1 = preBase[(long)((b0 + 1) * 512 + te) * 2048];
        float pv2 = preBase[(long)((b0 + 2) * 512 + te) * 2048];
        float pv3 = preBase[(long)((b0 + 3) * 512 + te) * 2048];

        float acc0 = 0.f, acc1 = 0.f, acc2 = 0.f, acc3 = 0.f;
        const float4* w4 = (const float4*)(sWhh + tid * WPITCH);
        const float4* h4 = (const float4*)sH;
#pragma unroll 8
        for (int k4 = 0; k4 < 64; ++k4) {
            float4 w  = w4[k4];
            float4 ha = h4[k4];
            float4 hb = h4[64 + k4];
            float4 hc = h4[128 + k4];
            float4 hd = h4[192 + k4];
            acc0 += w.x*ha.x + w.y*ha.y + w.z*ha.z + w.w*ha.w;
            acc1 += w.x*hb.x + w.y*hb.y + w.z*hb.z + w.w*hb.w;
            acc2 += w.x*hc.x + w.y*hc.y + w.z*hc.z + w.w*hc.w;
            acc3 += w.x*hd.x + w.y*hd.y + w.z*hd.z + w.w*hd.w;
        }
        float bbv = sBhh[tid];
        ((float4*)sG)[tid] = make_float4(acc0 + pv0 + bbv, acc1 + pv1 + bbv,
                                         acc2 + pv2 + bbv, acc3 + pv3 + bbv);
        __syncthreads();

        // elementwise update: thread -> (b = tid>>5, j2 = tid&31)
        {
            int b = tid >> 5, j2 = tid & 31;
            float gi = sG[(j2)        * 4 + b];
            float gf = sG[(32  + j2)  * 4 + b];
            float gg = sG[(64  + j2)  * 4 + b];
            float go = sG[(96  + j2)  * 4 + b];
            float c = sC[tid];
            c = sigm(gf) * c + sigm(gi) * tanhf(gg);
            float h = sigm(go) * tanhf(c);
            sC[tid] = c;
            sHown[par * 128 + b * 32 + j2] = h;
            out[(long)((b0 + b) * 512 + te) * 512 + dir * 256 + rank * 32 + j2] = h;
        }
        cluster.sync();

        if (t + 1 < 512) {
            for (int i = tid; i < 1024; i += 128) {
                int b = i >> 8, k = i & 255, peer = k >> 5, j3 = k & 31;
                const float* psH = (const float*)cluster.map_shared_rank(sHown, peer);
                sH[b * 256 + k] = psH[par * 128 + b * 32 + j3];
            }
            __syncthreads();
        }
        par ^= 1;
    }
}

// ---------------- softmax over 512-wide rows, in place ----------------
__global__ void __launch_bounds__(256) softmax512(float* __restrict__ Sc)
{
    __shared__ float red[256];
    const long base = (long)blockIdx.x * 512;
    const int tid = threadIdx.x;
    float v0 = Sc[base + tid], v1 = Sc[base + tid + 256];
    red[tid] = fmaxf(v0, v1);
    __syncthreads();
    for (int s = 128; s > 0; s >>= 1) {
        if (tid < s) red[tid] = fmaxf(red[tid], red[tid + s]);
        __syncthreads();
    }
    float m = red[0];
    __syncthreads();
    float e0 = expf(v0 - m), e1 = expf(v1 - m);
    red[tid] = e0 + e1;
    __syncthreads();
    for (int s = 128; s > 0; s >>= 1) {
        if (tid < s) red[tid] += red[tid + s];
        __syncthreads();
    }
    float inv = 1.f / red[0];
    Sc[base + tid]       = e0 * inv;
    Sc[base + tid + 256] = e1 * inv;
}

// ---------------- Wv column sum ----------------
__global__ void wvsum_kernel(const float* __restrict__ Wv, const float* __restrict__ bv)
{
    int k = threadIdx.x;  // 512
    float s = 0.f;
    for (int j = 0; j < 512; ++j) s += Wv[(long)j * 512 + k];
    g_wvsum[k] = s;
    if (k == 0) {
        float t = 0.f;
        for (int j = 0; j < 512; ++j) t += bv[j];
        g_bvsum[0] = t;
    }
}

// ---------------- intent head (per batch) + intent broadcast ----------------
__global__ void __launch_bounds__(256) intent_kernel(
    const float* __restrict__ out1, const float* __restrict__ Wg, const float* __restrict__ bg,
    const float* __restrict__ Wint, const float* __restrict__ bint,
    float* __restrict__ icl_out, float* __restrict__ int_out)
{
    __shared__ float sq[512], sw[512], sctx[512], siv[64], red[256];
    const int b = blockIdx.x, tid = threadIdx.x;
    const int lane = tid & 31, w = tid >> 5;
    const float* ob = out1 + (long)b * 512 * 512;

    sq[tid] = ob[(long)511 * 512 + tid];
    sq[tid + 256] = ob[(long)511 * 512 + tid + 256];
    __syncthreads();

    // iw pre-softmax scores: warp per s
    for (int s = w; s < 512; s += 8) {
        float sum = 0.f;
        for (int k = lane; k < 512; k += 32) sum += sq[k] * ob[(long)s * 512 + k];
#pragma unroll
        for (int off = 16; off; off >>= 1) sum += __shfl_xor_sync(0xffffffffu, sum, off);
        if (lane == 0) sw[s] = sum;
    }
    __syncthreads();

    // softmax over sw
    float v0 = sw[tid], v1 = sw[tid + 256];
    red[tid] = fmaxf(v0, v1);
    __syncthreads();
    for (int s = 128; s > 0; s >>= 1) { if (tid < s) red[tid] = fmaxf(red[tid], red[tid + s]); __syncthreads(); }
    float m = red[0];
    __syncthreads();
    float e0 = expf(v0 - m), e1 = expf(v1 - m);
    red[tid] = e0 + e1;
    __syncthreads();
    for (int s = 128; s > 0; s >>= 1) { if (tid < s) red[tid] += red[tid + s]; __syncthreads(); }
    float inv = 1.f / red[0];
    sw[tid] = e0 * inv; sw[tid + 256] = e1 * inv;
    __syncthreads();

    // intent_ctx
    float c0 = 0.f, c1 = 0.f;
    for (int s = 0; s < 512; ++s) {
        float wv = sw[s];
        c0 += wv * ob[(long)s * 512 + tid];
        c1 += wv * ob[(long)s * 512 + tid + 256];
    }
    sctx[tid] = c0; sctx[tid + 256] = c1;
    __syncthreads();

    // icl = Wg @ ictx + bg
    for (int j = w; j < 512; j += 8) {
        float sum = 0.f;
        for (int k = lane; k < 512; k += 32) sum += Wg[(long)j * 512 + k] * sctx[k];
#pragma unroll
        for (int off = 16; off; off >>= 1) sum += __shfl_xor_sync(0xffffffffu, sum, off);
        if (lane == 0) icl_out[b * 512 + j] = sum + bg[j];
    }
    // intent_vec = Wint @ (ictx + q) + bint
    for (int j = w; j < 64; j += 8) {
        float sum = 0.f;
        for (int k = lane; k < 512; k += 32) sum += Wint[(long)j * 512 + k] * (sctx[k] + sq[k]);
#pragma unroll
        for (int off = 16; off; off >>= 1) sum += __shfl_xor_sync(0xffffffffu, sum, off);
        if (lane == 0) siv[j] = sum + bint[j];
    }
    __syncthreads();

    // broadcast intent over time
    for (int i = tid; i < 512 * 64; i += 256) {
        int t = i >> 6, j = i & 63;
        int_out[((long)b * 512 + t) * 64 + j] = siv[j];
    }
}

// ---------------- gate + build A_tmp = gate*slot_ctx + out1 ----------------
__global__ void __launch_bounds__(256) gate_kernel(
    const float* __restrict__ ctx, const float* __restrict__ icl,
    const float* __restrict__ out1, float* __restrict__ Atmp)
{
    const int w = threadIdx.x >> 5, lane = threadIdx.x & 31;
    const long row = (long)blockIdx.x * 8 + w;
    const int b = (int)(row >> 9);
    const float* cr = ctx + row * 512;
    const float* ir = icl + (long)b * 512;
    float sum = 0.f;
    for (int k = lane; k < 512; k += 32)
        sum += tanhf(cr[k] + ir[k]) * g_wvsum[k];
#pragma unroll
    for (int off = 16; off; off >>= 1) sum += __shfl_xor_sync(0xffffffffu, sum, off);
    float gate = sum + g_bvsum[0];
    const float* orow = out1 + row * 512;
    float* arow = Atmp + row * 512;
    for (int k = lane; k < 512; k += 32)
        arow[k] = gate * cr[k] + orow[k];
}

// ---------------- host launcher ----------------
extern "C" void kernel_launch(void* const* d_in, const int* in_sizes, int n_in,
                              void* d_out, int out_size)
{
    const int*   src   = (const int*)  d_in[0];
    const float* emb   = (const float*)d_in[2];
    const float* Wih   = (const float*)d_in[3];
    const float* Whh   = (const float*)d_in[4];
    const float* bih   = (const float*)d_in[5];
    const float* bhh   = (const float*)d_in[6];
    const float* Wg    = (const float*)d_in[7];
    const float* bg    = (const float*)d_in[8];
    const float* Wv    = (const float*)d_in[9];
    const float* bv    = (const float*)d_in[10];
    const float* Wslot = (const float*)d_in[11];
    const float* bslot = (const float*)d_in[12];
    const float* Wint  = (const float*)d_in[13];
    const float* bint  = (const float*)d_in[14];

    float* out       = (float*)d_out;
    float* slot_out  = out;                      // (B,S,128)
    float* int_out   = out + (size_t)MM * NSLOT; // (B,S,64)

    float *p_pre = 0, *p_out0 = 0, *p_out1 = 0, *p_scores = 0, *p_slotctx = 0, *p_icl = 0;
    (void)cudaGetSymbolAddress((void**)&p_pre,     g_pre);
    (void)cudaGetSymbolAddress((void**)&p_out0,    g_out0);
    (void)cudaGetSymbolAddress((void**)&p_out1,    g_out1);
    (void)cudaGetSymbolAddress((void**)&p_scores,  g_scores);
    (void)cudaGetSymbolAddress((void**)&p_slotctx, g_slotctx);
    (void)cudaGetSymbolAddress((void**)&p_icl,     g_icl);

    const size_t lstm_smem = (size_t)LSTM_SMEM_FLOATS * sizeof(float);
    (void)cudaFuncSetAttribute((const void*)lstm_kernel,
                               cudaFuncAttributeMaxDynamicSharedMemorySize, (int)lstm_smem);

    // wv colsum (independent)
    wvsum_kernel<<<1, 512>>>(Wv, bv);

    // layer-0 input projection (embedding gather fused)
    {
        dim3 grid(2048 / 128, MM / 128, 1);
        gemm_kernel<true, true><<<grid, 256>>>(nullptr, Wih, bih, p_pre,
                                               MM, 2048, EE, 0, 0, 0, src, emb);
    }
    // layer-0 recurrence
    lstm_kernel<<<128, 128, lstm_smem>>>(p_pre, Whh, bhh, p_out0);

    // layer-1 input projection
    {
        dim3 grid(2048 / 128, MM / 128, 1);
        gemm_kernel<true, false><<<grid, 256>>>(p_out0, Wih + (size_t)2048 * 512,
                                                bih + 2048, p_pre,
                                                MM, 2048, H2, 0, 0, 0, nullptr, nullptr);
    }
    // layer-1 recurrence
    lstm_kernel<<<128, 128, lstm_smem>>>(p_pre, Whh + (size_t)2 * H4 * HH,
                                         bhh + 2048, p_out1);

    // attention scores: per-batch out @ out^T
    {
        dim3 grid(512 / 128, 512 / 128, BB);
        gemm_kernel<true, false><<<grid, 256>>>(p_out1, p_out1, nullptr, p_scores,
                                                512, 512, 512,
                                                (long)512 * 512, (long)512 * 512, (long)512 * 512,
                                                nullptr, nullptr);
    }
    // row softmax
    softmax512<<<MM, 256>>>(p_scores);

    // slot_ctx = w @ out
    {
        dim3 grid(512 / 128, 512 / 128, BB);
        gemm_kernel<false, false><<<grid, 256>>>(p_scores, p_out1, nullptr, p_slotctx,
                                                 512, 512, 512,
                                                 (long)512 * 512, (long)512 * 512, (long)512 * 512,
                                                 nullptr, nullptr);
    }
    // intent head (also writes broadcast intent output + icl)
    intent_kernel<<<BB, 256>>>(p_out1, Wg, bg, Wint, bint, p_icl, int_out);

    // gate + A_tmp (reuses scores buffer)
    gate_kernel<<<MM / 8, 256>>>(p_slotctx, p_icl, p_out1, p_scores);

    // slot_outputs = A_tmp @ Wslot^T + bslot
    {
        dim3 grid(NSLOT / 128, MM / 128, 1);
        gemm_kernel<true, false><<<grid, 256>>>(p_scores, Wslot, bslot, slot_out,
                                                MM, NSLOT, H2, 0, 0, 0, nullptr, nullptr);
    }
}

// round 3
// speedup vs baseline: 1.1154x; 1.1154x over previous
#include <cuda_runtime.h>
#include <cooperative_groups.h>
#include <math.h>

namespace cg = cooperative_groups;

// ---------------- Problem constants ----------------
#define BB    32
#define SS    512
#define EE    512
#define HH    256
#define H4    1024
#define H2    512
#define MM    (BB*SS)      // 16384
#define NSLOT 128
#define NINT  64

// ---------------- Scratch (device globals; no allocation allowed) ----------------
__device__ float g_pre[(size_t)MM*2048];     // input-proj output, both dirs (128MB)
__device__ float g_out0[(size_t)MM*H2];      // layer-0 output
__device__ float g_out1[(size_t)MM*H2];      // layer-1 output (encoder out)
__device__ float g_scores[(size_t)MM*H2];    // attention scores (B,512,512); reused as A_tmp
__device__ float g_slotctx[(size_t)MM*H2];   // slot context
__device__ float g_icl[BB*H2];
__device__ float g_wvsum[H2];
__device__ float g_bvsum[1];

// ---------------- Generic fp32 GEMM: C = A @ op(B) + bias ----------------
template<bool TRANSB, bool GATHER>
__global__ void __launch_bounds__(256) gemm_kernel(
    const float* __restrict__ A, const float* __restrict__ Bm,
    const float* __restrict__ bias, float* __restrict__ C,
    int M, int N, int K,
    long sA, long sB, long sC,
    const int* __restrict__ gidx, const float* __restrict__ gtab)
{
    __shared__ float As[16][128];
    __shared__ float Bs[16][128];

    const int tid = threadIdx.x;
    const int tx = tid & 15, ty = tid >> 4;
    const int nbase = blockIdx.x * 128;
    const int mbase = blockIdx.y * 128;

    const float* Ab = GATHER ? gtab : (A + blockIdx.z * sA);
    const float* Bb = Bm + blockIdx.z * sB;
    float*       Cb = C  + blockIdx.z * sC;

    float acc[8][8];
#pragma unroll
    for (int i = 0; i < 8; ++i)
#pragma unroll
        for (int j = 0; j < 8; ++j) acc[i][j] = 0.f;

    const int rowA0 = tid >> 2;
    const int rowA1 = rowA0 + 64;
    const int kqA   = (tid & 3) * 4;
    long aoff0, aoff1;
    if (GATHER) {
        aoff0 = (long)gidx[mbase + rowA0] * K;
        aoff1 = (long)gidx[mbase + rowA1] * K;
    } else {
        aoff0 = (long)(mbase + rowA0) * K;
        aoff1 = (long)(mbase + rowA1) * K;
    }
    long boff0 = 0, boff1 = 0; int kB0 = 0, kB1 = 0, n4 = 0;
    if (TRANSB) {
        boff0 = (long)(nbase + rowA0) * K;
        boff1 = (long)(nbase + rowA1) * K;
    } else {
        kB0 = tid >> 5;
        kB1 = kB0 + 8;
        n4  = tid & 31;
    }

    for (int kt = 0; kt < K; kt += 16) {
        float4 a0 = *(const float4*)(Ab + aoff0 + kt + kqA);
        float4 a1 = *(const float4*)(Ab + aoff1 + kt + kqA);
        As[kqA+0][rowA0] = a0.x; As[kqA+1][rowA0] = a0.y;
        As[kqA+2][rowA0] = a0.z; As[kqA+3][rowA0] = a0.w;
        As[kqA+0][rowA1] = a1.x; As[kqA+1][rowA1] = a1.y;
        As[kqA+2][rowA1] = a1.z; As[kqA+3][rowA1] = a1.w;

        if (TRANSB) {
            float4 b0 = *(const float4*)(Bb + boff0 + kt + kqA);
            float4 b1 = *(const float4*)(Bb + boff1 + kt + kqA);
            Bs[kqA+0][rowA0] = b0.x; Bs[kqA+1][rowA0] = b0.y;
            Bs[kqA+2][rowA0] = b0.z; Bs[kqA+3][rowA0] = b0.w;
            Bs[kqA+0][rowA1] = b1.x; Bs[kqA+1][rowA1] = b1.y;
            Bs[kqA+2][rowA1] = b1.z; Bs[kqA+3][rowA1] = b1.w;
        } else {
            float4 b0 = *(const float4*)(Bb + (long)(kt + kB0) * N + nbase + n4 * 4);
            float4 b1 = *(const float4*)(Bb + (long)(kt + kB1) * N + nbase + n4 * 4);
            *(float4*)&Bs[kB0][n4 * 4] = b0;
            *(float4*)&Bs[kB1][n4 * 4] = b1;
        }
        __syncthreads();

#pragma unroll
        for (int k = 0; k < 16; ++k) {
            float4 av0 = *(const float4*)&As[k][ty * 8];
            float4 av1 = *(const float4*)&As[k][ty * 8 + 4];
            float4 bv0 = *(const float4*)&Bs[k][tx * 8];
            float4 bv1 = *(const float4*)&Bs[k][tx * 8 + 4];
            float aR[8] = {av0.x, av0.y, av0.z, av0.w, av1.x, av1.y, av1.z, av1.w};
            float bR[8] = {bv0.x, bv0.y, bv0.z, bv0.w, bv1.x, bv1.y, bv1.z, bv1.w};
#pragma unroll
            for (int i = 0; i < 8; ++i)
#pragma unroll
                for (int j = 0; j < 8; ++j)
                    acc[i][j] += aR[i] * bR[j];
        }
        __syncthreads();
    }

    float bb[8];
#pragma unroll
    for (int j = 0; j < 8; ++j) bb[j] = bias ? bias[nbase + tx * 8 + j] : 0.f;

#pragma unroll
    for (int i = 0; i < 8; ++i) {
        long m = mbase + ty * 8 + i;
        float* crow = Cb + m * (long)N + nbase + tx * 8;
        float4 r0 = make_float4(acc[i][0] + bb[0], acc[i][1] + bb[1],
                                acc[i][2] + bb[2], acc[i][3] + bb[3]);
        float4 r1 = make_float4(acc[i][4] + bb[4], acc[i][5] + bb[5],
                                acc[i][6] + bb[6], acc[i][7] + bb[7]);
        *(float4*)crow       = r0;
        *(float4*)(crow + 4) = r1;
    }
}

// ---------------- BiLSTM recurrence, v2 ----------------
// 16 clusters x 8 CTAs (128 SMs). cluster: dir = cid&1, batches b0..b0+3.
// CTA rank owns 128 gate rows: type*256 + rank*32 + j  (type 0..3, j 0..31).
// 512 threads: tid = r*4 + kq  (r = gate row 0..127, kq = k-quarter 0..3).
// Whh slice register-resident (64 floats/thread). h in SMEM, skewed layout:
//   off(b,k) = b*272 + (k>>6)*68 + (k&63)   (float units) -> conflict-free LDS.128.
// k-split reduced by shfl butterfly (lanes tid^1, tid^2).
// Exchange: producers push h into all 8 peers' next buffer (DSMEM stores),
// double-buffered, one cluster.sync per step.
__device__ __forceinline__ float sigm(float x) { return 1.f / (1.f + expf(-x)); }

#define HB_F4   68              // float4s per batch in h buffer (4*17)
#define HBUF_F4 (4*HB_F4)       // 272 float4s per buffer
#define GP      136             // sG pitch per batch (floats)

__global__ void __cluster_dims__(8, 1, 1) __launch_bounds__(512, 1)
lstm_kernel(const float* __restrict__ pre, const float* __restrict__ Whh,
            const float* __restrict__ bhh, float* __restrict__ out)
{
    __shared__ float4 sHbuf[2][HBUF_F4];    // h, skewed, double-buffered
    __shared__ float  sG[4*GP];             // gate pre-activations [b][136]
    __shared__ float  sBhh[128];            // per gate-row bias
    __shared__ float  sC[128];              // cell state [b*32+j]

    cg::cluster_group cluster = cg::this_cluster();
    const int rank = cluster.block_rank();
    const int cid  = blockIdx.x >> 3;
    const int dir  = cid & 1;
    const int b0   = (cid >> 1) * 4;
    const int tid  = threadIdx.x;

    const int r  = tid >> 2;                // gate row 0..127
    const int kq = tid & 3;                 // k quarter
    const int type = r >> 5, jj = r & 31;
    const int grow = type * 256 + rank * 32 + jj;   // row in Whh/bias/pre (within dir)

    // ---- register-resident Whh slice: 64 floats = 16 float4 ----
    float4 wr[16];
    {
        const float4* W4 = (const float4*)(Whh + ((long)(dir * 1024 + grow)) * 256) + kq * 16;
#pragma unroll
        for (int i = 0; i < 16; ++i) wr[i] = W4[i];
    }

    if (tid < 128) {
        sBhh[tid] = bhh[dir * 1024 + (tid >> 5) * 256 + rank * 32 + (tid & 31)];
        sC[tid] = 0.f;
    }
    {   // zero both h buffers
        float4 z = make_float4(0.f, 0.f, 0.f, 0.f);
        for (int i = tid; i < 2 * HBUF_F4; i += 512) ((float4*)sHbuf)[i] = z;
    }
    __syncthreads();
    cluster.sync();   // peers must not push into our buffers before init done

    const int hbase = kq * 17;              // float4 offset of this thread's k block
    int par = 0;

    for (int t = 0; t < 512; ++t) {
        const int te = dir ? (511 - t) : t;

        // prefetch pre for the update phase (tid<128: one (b,j) pair)
        float p0, p1, p2, p3;
        if (tid < 128) {
            const int ub = tid >> 5, uj = tid & 31;
            const float* pb = pre + ((long)((b0 + ub) * 512 + te)) * 2048
                                  + dir * 1024 + rank * 32 + uj;
            p0 = pb[0]; p1 = pb[256]; p2 = pb[512]; p3 = pb[768];
        }

        // ---- gate dots: 4 batches x 64 k (weights in registers) ----
        const float4* hb = sHbuf[par];
        float acc0 = 0.f, acc1 = 0.f, acc2 = 0.f, acc3 = 0.f;
#pragma unroll
        for (int k4 = 0; k4 < 16; ++k4) {
            float4 w  = wr[k4];
            float4 h0 = hb[hbase + k4];
            float4 h1 = hb[hbase + HB_F4 + k4];
            float4 h2 = hb[hbase + 2*HB_F4 + k4];
            float4 h3 = hb[hbase + 3*HB_F4 + k4];
            acc0 += w.x*h0.x + w.y*h0.y + w.z*h0.z + w.w*h0.w;
            acc1 += w.x*h1.x + w.y*h1.y + w.z*h1.z + w.w*h1.w;
            acc2 += w.x*h2.x + w.y*h2.y + w.z*h2.z + w.w*h2.w;
            acc3 += w.x*h3.x + w.y*h3.y + w.z*h3.z + w.w*h3.w;
        }
        // butterfly over the 4 kq lanes (tid^1, tid^2 are same warp)
        acc0 += __shfl_xor_sync(0xffffffffu, acc0, 1);
        acc0 += __shfl_xor_sync(0xffffffffu, acc0, 2);
        acc1 += __shfl_xor_sync(0xffffffffu, acc1, 1);
        acc1 += __shfl_xor_sync(0xffffffffu, acc1, 2);
        acc2 += __shfl_xor_sync(0xffffffffu, acc2, 1);
        acc2 += __shfl_xor_sync(0xffffffffu, acc2, 2);
        acc3 += __shfl_xor_sync(0xffffffffu, acc3, 1);
        acc3 += __shfl_xor_sync(0xffffffffu, acc3, 2);
        // lane kq stores batch kq's gate value (conflict-free: bank = 8*kq + r mod 32)
        float gv = (kq == 0) ? acc0 : (kq == 1) ? acc1 : (kq == 2) ? acc2 : acc3;
        sG[kq * GP + r] = gv;
        __syncthreads();

        // ---- elementwise update + push h to all peers ----
        if (tid < 128) {
            const int ub = tid >> 5, uj = tid & 31;
            const float bi = sBhh[uj],      bf = sBhh[32 + uj];
            const float bg2 = sBhh[64 + uj], bo = sBhh[96 + uj];
            float gi = sG[ub * GP + uj]       + p0 + bi;
            float gf = sG[ub * GP + 32 + uj]  + p1 + bf;
            float gg = sG[ub * GP + 64 + uj]  + p2 + bg2;
            float go = sG[ub * GP + 96 + uj]  + p3 + bo;
            float c = sC[tid];
            c = sigm(gf) * c + sigm(gi) * tanhf(gg);
            float h = sigm(go) * tanhf(c);
            sC[tid] = c;
            out[((long)((b0 + ub) * 512 + te)) * 512 + dir * 256 + rank * 32 + uj] = h;
            // push into every peer's next buffer
            const int kg = rank * 32 + uj;                    // global k index 0..255
            const int off = ub * 272 + (kg >> 6) * 68 + (kg & 63);  // float units
            float* dstbase = (float*)sHbuf[par ^ 1];
#pragma unroll
            for (int peer = 0; peer < 8; ++peer) {
                float* pdst = (float*)cluster.map_shared_rank(dstbase, peer);
                pdst[off] = h;
            }
        }
        cluster.sync();
        par ^= 1;
    }
}

// ---------------- softmax over 512-wide rows, in place ----------------
__global__ void __launch_bounds__(256) softmax512(float* __restrict__ Sc)
{
    __shared__ float red[256];
    const long base = (long)blockIdx.x * 512;
    const int tid = threadIdx.x;
    float v0 = Sc[base + tid], v1 = Sc[base + tid + 256];
    red[tid] = fmaxf(v0, v1);
    __syncthreads();
    for (int s = 128; s > 0; s >>= 1) {
        if (tid < s) red[tid] = fmaxf(red[tid], red[tid + s]);
        __syncthreads();
    }
    float m = red[0];
    __syncthreads();
    float e0 = expf(v0 - m), e1 = expf(v1 - m);
    red[tid] = e0 + e1;
    __syncthreads();
    for (int s = 128; s > 0; s >>= 1) {
        if (tid < s) red[tid] += red[tid + s];
        __syncthreads();
    }
    float inv = 1.f / red[0];
    Sc[base + tid]       = e0 * inv;
    Sc[base + tid + 256] = e1 * inv;
}

// ---------------- Wv column sum ----------------
__global__ void wvsum_kernel(const float* __restrict__ Wv, const float* __restrict__ bv)
{
    int k = threadIdx.x;  // 512
    float s = 0.f;
    for (int j = 0; j < 512; ++j) s += Wv[(long)j * 512 + k];
    g_wvsum[k] = s;
    if (k == 0) {
        float t = 0.f;
        for (int j = 0; j < 512; ++j) t += bv[j];
        g_bvsum[0] = t;
    }
}

// ---------------- intent head (per batch) + intent broadcast ----------------
__global__ void __launch_bounds__(256) intent_kernel(
    const float* __restrict__ out1, const float* __restrict__ Wg, const float* __restrict__ bg,
    const float* __restrict__ Wint, const float* __restrict__ bint,
    float* __restrict__ icl_out, float* __restrict__ int_out)
{
    __shared__ float sq[512], sw[512], sctx[512], siv[64], red[256];
    const int b = blockIdx.x, tid = threadIdx.x;
    const int lane = tid & 31, w = tid >> 5;
    const float* ob = out1 + (long)b * 512 * 512;

    sq[tid] = ob[(long)511 * 512 + tid];
    sq[tid + 256] = ob[(long)511 * 512 + tid + 256];
    __syncthreads();

    for (int s = w; s < 512; s += 8) {
        float sum = 0.f;
        for (int k = lane; k < 512; k += 32) sum += sq[k] * ob[(long)s * 512 + k];
#pragma unroll
        for (int off = 16; off; off >>= 1) sum += __shfl_xor_sync(0xffffffffu, sum, off);
        if (lane == 0) sw[s] = sum;
    }
    __syncthreads();

    float v0 = sw[tid], v1 = sw[tid + 256];
    red[tid] = fmaxf(v0, v1);
    __syncthreads();
    for (int s = 128; s > 0; s >>= 1) { if (tid < s) red[tid] = fmaxf(red[tid], red[tid + s]); __syncthreads(); }
    float m = red[0];
    __syncthreads();
    float e0 = expf(v0 - m), e1 = expf(v1 - m);
    red[tid] = e0 + e1;
    __syncthreads();
    for (int s = 128; s > 0; s >>= 1) { if (tid < s) red[tid] += red[tid + s]; __syncthreads(); }
    float inv = 1.f / red[0];
    sw[tid] = e0 * inv; sw[tid + 256] = e1 * inv;
    __syncthreads();

    float c0 = 0.f, c1 = 0.f;
    for (int s = 0; s < 512; ++s) {
        float wv = sw[s];
        c0 += wv * ob[(long)s * 512 + tid];
        c1 += wv * ob[(long)s * 512 + tid + 256];
    }
    sctx[tid] = c0; sctx[tid + 256] = c1;
    __syncthreads();

    for (int j = w; j < 512; j += 8) {
        float sum = 0.f;
        for (int k = lane; k < 512; k += 32) sum += Wg[(long)j * 512 + k] * sctx[k];
#pragma unroll
        for (int off = 16; off; off >>= 1) sum += __shfl_xor_sync(0xffffffffu, sum, off);
        if (lane == 0) icl_out[b * 512 + j] = sum + bg[j];
    }
    for (int j = w; j < 64; j += 8) {
        float sum = 0.f;
        for (int k = lane; k < 512; k += 32) sum += Wint[(long)j * 512 + k] * (sctx[k] + sq[k]);
#pragma unroll
        for (int off = 16; off; off >>= 1) sum += __shfl_xor_sync(0xffffffffu, sum, off);
        if (lane == 0) siv[j] = sum + bint[j];
    }
    __syncthreads();

    for (int i = tid; i < 512 * 64; i += 256) {
        int t = i >> 6, j = i & 63;
        int_out[((long)b * 512 + t) * 64 + j] = siv[j];
    }
}

// ---------------- gate + build A_tmp = gate*slot_ctx + out1 ----------------
__global__ void __launch_bounds__(256) gate_kernel(
    const float* __restrict__ ctx, const float* __restrict__ icl,
    const float* __restrict__ out1, float* __restrict__ Atmp)
{
    const int w = threadIdx.x >> 5, lane = threadIdx.x & 31;
    const long row = (long)blockIdx.x * 8 + w;
    const int b = (int)(row >> 9);
    const float* cr = ctx + row * 512;
    const float* ir = icl + (long)b * 512;
    float sum = 0.f;
    for (int k = lane; k < 512; k += 32)
        sum += tanhf(cr[k] + ir[k]) * g_wvsum[k];
#pragma unroll
    for (int off = 16; off; off >>= 1) sum += __shfl_xor_sync(0xffffffffu, sum, off);
    float gate = sum + g_bvsum[0];
    const float* orow = out1 + row * 512;
    float* arow = Atmp + row * 512;
    for (int k = lane; k < 512; k += 32)
        arow[k] = gate * cr[k] + orow[k];
}

// ---------------- host launcher ----------------
extern "C" void kernel_launch(void* const* d_in, const int* in_sizes, int n_in,
                              void* d_out, int out_size)
{
    const int*   src   = (const int*)  d_in[0];
    const float* emb   = (const float*)d_in[2];
    const float* Wih   = (const float*)d_in[3];
    const float* Whh   = (const float*)d_in[4];
    const float* bih   = (const float*)d_in[5];
    const float* bhh   = (const float*)d_in[6];
    const float* Wg    = (const float*)d_in[7];
    const float* bg    = (const float*)d_in[8];
    const float* Wv    = (const float*)d_in[9];
    const float* bv    = (const float*)d_in[10];
    const float* Wslot = (const float*)d_in[11];
    const float* bslot = (const float*)d_in[12];
    const float* Wint  = (const float*)d_in[13];
    const float* bint  = (const float*)d_in[14];

    float* out       = (float*)d_out;
    float* slot_out  = out;                      // (B,S,128)
    float* int_out   = out + (size_t)MM * NSLOT; // (B,S,64)

    float *p_pre = 0, *p_out0 = 0, *p_out1 = 0, *p_scores = 0, *p_slotctx = 0, *p_icl = 0;
    (void)cudaGetSymbolAddress((void**)&p_pre,     g_pre);
    (void)cudaGetSymbolAddress((void**)&p_out0,    g_out0);
    (void)cudaGetSymbolAddress((void**)&p_out1,    g_out1);
    (void)cudaGetSymbolAddress((void**)&p_scores,  g_scores);
    (void)cudaGetSymbolAddress((void**)&p_slotctx, g_slotctx);
    (void)cudaGetSymbolAddress((void**)&p_icl,     g_icl);

    // wv colsum (independent)
    wvsum_kernel<<<1, 512>>>(Wv, bv);

    // layer-0 input projection (embedding gather fused)
    {
        dim3 grid(2048 / 128, MM / 128, 1);
        gemm_kernel<true, true><<<grid, 256>>>(nullptr, Wih, bih, p_pre,
                                               MM, 2048, EE, 0, 0, 0, src, emb);
    }
    // layer-0 recurrence
    lstm_kernel<<<128, 512>>>(p_pre, Whh, bhh, p_out0);

    // layer-1 input projection
    {
        dim3 grid(2048 / 128, MM / 128, 1);
        gemm_kernel<true, false><<<grid, 256>>>(p_out0, Wih + (size_t)2048 * 512,
                                                bih + 2048, p_pre,
                                                MM, 2048, H2, 0, 0, 0, nullptr, nullptr);
    }
    // layer-1 recurrence
    lstm_kernel<<<128, 512>>>(p_pre, Whh + (size_t)2 * H4 * HH,
                              bhh + 2048, p_out1);

    // attention scores: per-batch out @ out^T
    {
        dim3 grid(512 / 128, 512 / 128, BB);
        gemm_kernel<true, false><<<grid, 256>>>(p_out1, p_out1, nullptr, p_scores,
                                                512, 512, 512,
                                                (long)512 * 512, (long)512 * 512, (long)512 * 512,
                                                nullptr, nullptr);
    }
    // row softmax
    softmax512<<<MM, 256>>>(p_scores);

    // slot_ctx = w @ out
    {
        dim3 grid(512 / 128, 512 / 128, BB);
        gemm_kernel<false, false><<<grid, 256>>>(p_scores, p_out1, nullptr, p_slotctx,
                                                 512, 512, 512,
                                                 (long)512 * 512, (long)512 * 512, (long)512 * 512,
                                                 nullptr, nullptr);
    }
    // intent head (also writes broadcast intent output + icl)
    intent_kernel<<<BB, 256>>>(p_out1, Wg, bg, Wint, bint, p_icl, int_out);

    // gate + A_tmp (reuses scores buffer)
    gate_kernel<<<MM / 8, 256>>>(p_slotctx, p_icl, p_out1, p_scores);

    // slot_outputs = A_tmp @ Wslot^T + bslot
    {
        dim3 grid(NSLOT / 128, MM / 128, 1);
        gemm_kernel<true, false><<<grid, 256>>>(p_scores, Wslot, bslot, slot_out,
                                                MM, NSLOT, H2, 0, 0, 0, nullptr, nullptr);
    }
}

// round 5
// speedup vs baseline: 1.5823x; 1.4186x over previous
#include <cuda_runtime.h>
#include <cooperative_groups.h>
#include <math.h>

namespace cg = cooperative_groups;

// ---------------- Problem constants ----------------
#define BB    32
#define SS    512
#define EE    512
#define HH    256
#define H4    1024
#define H2    512
#define MM    (BB*SS)      // 16384
#define NSLOT 128
#define NINT  64

// ---------------- Scratch (device globals; no allocation allowed) ----------------
__device__ float g_pre[(size_t)MM*2048];
__device__ float g_out0[(size_t)MM*H2];
__device__ float g_out1[(size_t)MM*H2];
__device__ float g_scores[(size_t)MM*H2];
__device__ float g_slotctx[(size_t)MM*H2];
__device__ float g_icl[BB*H2];
__device__ float g_wvsum[H2];
__device__ float g_bvsum[1];

// ---------------- packed f32x2 helpers ----------------
#define FMAX2(d, a, b, c) \
    asm("fma.rn.f32x2 %0, %1, %2, %3;" : "=l"(d) : "l"(a), "l"(b), "l"(c))
#define F4TOX2(v, a, b) \
    asm("mov.b64 %0, {%2, %3};\n\tmov.b64 %1, {%4, %5};" \
        : "=l"(a), "=l"(b) : "f"((v).x), "f"((v).y), "f"((v).z), "f"((v).w))
#define UNPX2(lo, hi, v) \
    asm("mov.b64 {%0, %1}, %2;" : "=f"(lo), "=f"(hi) : "l"(v))

#define CLUSTER_ARRIVE() asm volatile("barrier.cluster.arrive.aligned;" ::: "memory")
#define CLUSTER_WAIT()   asm volatile("barrier.cluster.wait.aligned;"   ::: "memory")

__device__ __forceinline__ float sigm_f(float x) {
    return __fdividef(1.f, 1.f + __expf(-x));
}
__device__ __forceinline__ float tanh_f(float x) {
    return __fdividef(2.f, 1.f + __expf(-2.f * x)) - 1.f;
}

// ---------------- Generic fp32 GEMM ----------------
template<bool TRANSB, bool GATHER>
__global__ void __launch_bounds__(256) gemm_kernel(
    const float* __restrict__ A, const float* __restrict__ Bm,
    const float* __restrict__ bias, float* __restrict__ C,
    int M, int N, int K,
    long sA, long sB, long sC,
    const int* __restrict__ gidx, const float* __restrict__ gtab)
{
    __shared__ float As[16][128];
    __shared__ float Bs[16][128];

    const int tid = threadIdx.x;
    const int tx = tid & 15, ty = tid >> 4;
    const int nbase = blockIdx.x * 128;
    const int mbase = blockIdx.y * 128;

    const float* Ab = GATHER ? gtab : (A + blockIdx.z * sA);
    const float* Bb = Bm + blockIdx.z * sB;
    float*       Cb = C  + blockIdx.z * sC;

    float acc[8][8];
#pragma unroll
    for (int i = 0; i < 8; ++i)
#pragma unroll
        for (int j = 0; j < 8; ++j) acc[i][j] = 0.f;

    const int rowA0 = tid >> 2;
    const int rowA1 = rowA0 + 64;
    const int kqA   = (tid & 3) * 4;
    long aoff0, aoff1;
    if (GATHER) {
        aoff0 = (long)gidx[mbase + rowA0] * K;
        aoff1 = (long)gidx[mbase + rowA1] * K;
    } else {
        aoff0 = (long)(mbase + rowA0) * K;
        aoff1 = (long)(mbase + rowA1) * K;
    }
    long boff0 = 0, boff1 = 0; int kB0 = 0, kB1 = 0, n4 = 0;
    if (TRANSB) {
        boff0 = (long)(nbase + rowA0) * K;
        boff1 = (long)(nbase + rowA1) * K;
    } else {
        kB0 = tid >> 5;
        kB1 = kB0 + 8;
        n4  = tid & 31;
    }

    for (int kt = 0; kt < K; kt += 16) {
        float4 a0 = *(const float4*)(Ab + aoff0 + kt + kqA);
        float4 a1 = *(const float4*)(Ab + aoff1 + kt + kqA);
        As[kqA+0][rowA0] = a0.x; As[kqA+1][rowA0] = a0.y;
        As[kqA+2][rowA0] = a0.z; As[kqA+3][rowA0] = a0.w;
        As[kqA+0][rowA1] = a1.x; As[kqA+1][rowA1] = a1.y;
        As[kqA+2][rowA1] = a1.z; As[kqA+3][rowA1] = a1.w;

        if (TRANSB) {
            float4 b0 = *(const float4*)(Bb + boff0 + kt + kqA);
            float4 b1 = *(const float4*)(Bb + boff1 + kt + kqA);
            Bs[kqA+0][rowA0] = b0.x; Bs[kqA+1][rowA0] = b0.y;
            Bs[kqA+2][rowA0] = b0.z; Bs[kqA+3][rowA0] = b0.w;
            Bs[kqA+0][rowA1] = b1.x; Bs[kqA+1][rowA1] = b1.y;
            Bs[kqA+2][rowA1] = b1.z; Bs[kqA+3][rowA1] = b1.w;
        } else {
            float4 b0 = *(const float4*)(Bb + (long)(kt + kB0) * N + nbase + n4 * 4);
            float4 b1 = *(const float4*)(Bb + (long)(kt + kB1) * N + nbase + n4 * 4);
            *(float4*)&Bs[kB0][n4 * 4] = b0;
            *(float4*)&Bs[kB1][n4 * 4] = b1;
        }
        __syncthreads();

#pragma unroll
        for (int k = 0; k < 16; ++k) {
            float4 av0 = *(const float4*)&As[k][ty * 8];
            float4 av1 = *(const float4*)&As[k][ty * 8 + 4];
            float4 bv0 = *(const float4*)&Bs[k][tx * 8];
            float4 bv1 = *(const float4*)&Bs[k][tx * 8 + 4];
            float aR[8] = {av0.x, av0.y, av0.z, av0.w, av1.x, av1.y, av1.z, av1.w};
            float bR[8] = {bv0.x, bv0.y, bv0.z, bv0.w, bv1.x, bv1.y, bv1.z, bv1.w};
#pragma unroll
            for (int i = 0; i < 8; ++i)
#pragma unroll
                for (int j = 0; j < 8; ++j)
                    acc[i][j] += aR[i] * bR[j];
        }
        __syncthreads();
    }

    float bb[8];
#pragma unroll
    for (int j = 0; j < 8; ++j) bb[j] = bias ? bias[nbase + tx * 8 + j] : 0.f;

#pragma unroll
    for (int i = 0; i < 8; ++i) {
        long m = mbase + ty * 8 + i;
        float* crow = Cb + m * (long)N + nbase + tx * 8;
        float4 r0 = make_float4(acc[i][0] + bb[0], acc[i][1] + bb[1],
                                acc[i][2] + bb[2], acc[i][3] + bb[3]);
        float4 r1 = make_float4(acc[i][4] + bb[4], acc[i][5] + bb[5],
                                acc[i][6] + bb[6], acc[i][7] + bb[7]);
        *(float4*)crow       = r0;
        *(float4*)(crow + 4) = r1;
    }
}

// ---------------- BiLSTM recurrence, v3b (early fold, lower reg pressure) ----------------
#define HB_PITCH 5                 // float4 per 16-float k-slice
#define HB_BATCH (16*HB_PITCH)     // 80 float4 per batch
#define HB_TOT   (4*HB_BATCH)      // 320 float4 per buffer
#define GPF      132               // sGp pitch (floats) per (q,b)

__global__ void __cluster_dims__(8, 1, 1) __launch_bounds__(512, 1)
lstm_kernel(const float* __restrict__ pre, const float* __restrict__ Whh,
            const float* __restrict__ bhh, float* __restrict__ out)
{
    __shared__ float4 sHbuf[2][HB_TOT];     // 10 KB
    __shared__ float  sGp[16*GPF];          // partials [q*4+b][132]
    __shared__ float  sAct[4*GPF];          // activated gates [b][132]
    __shared__ float  sStage[128];          // h, [b*32+j]
    __shared__ float  sBhh[128];
    __shared__ float  sC[128];

    cg::cluster_group cluster = cg::this_cluster();
    const int rank = cluster.block_rank();
    const int cid  = blockIdx.x >> 3;
    const int dir  = cid & 1;
    const int b0   = (cid >> 1) * 4;
    const int tid  = threadIdx.x;

    const int rg = tid >> 4;        // 0..31
    const int ks = tid & 15;        // 0..15
    const int r0 = rg * 4;
    // phase-B identity
    const int pb = tid >> 7;        // 0..3
    const int pr = tid & 127;       // 0..127
    const int grow_pr = (pr >> 5) * 256 + rank * 32 + (pr & 31);

    // ---- register-resident weights, f32x2 packed over k-pairs ----
    unsigned long long wr2[4][8];
    {
        const int type0 = r0 >> 5;
#pragma unroll
        for (int i = 0; i < 4; ++i) {
            const int gr = type0 * 256 + rank * 32 + ((r0 + i) & 31);
            const float4* W4 = (const float4*)(Whh + ((long)(dir * 1024 + gr)) * 256 + ks * 16);
#pragma unroll
            for (int q = 0; q < 4; ++q) {
                float4 w = W4[q];
                F4TOX2(w, wr2[i][q * 2], wr2[i][q * 2 + 1]);
            }
        }
    }
    if (tid < 128) {
        sBhh[tid] = bhh[dir * 1024 + (tid >> 5) * 256 + rank * 32 + (tid & 31)];
        sC[tid] = 0.f;
    }
    {
        float4 z = make_float4(0.f, 0.f, 0.f, 0.f);
        for (int i = tid; i < 2 * HB_TOT; i += 512) ((float4*)sHbuf)[i] = z;
    }
    __syncthreads();
    CLUSTER_ARRIVE(); CLUSTER_WAIT();

    // per-step streaming pointers
    const long pstride = dir ? -2048L : 2048L;
    const float* pp = pre + ((long)((b0 + pb) * 512 + (dir ? 511 : 0))) * 2048
                          + dir * 1024 + grow_pr;
    float* op = out;
    long ostride = 0;
    if (tid < 128) {
        const int cb = tid >> 5, cj = tid & 31;
        op = out + ((long)((b0 + cb) * 512 + (dir ? 511 : 0))) * 512
                 + dir * 256 + rank * 32 + cj;
        ostride = dir ? -512L : 512L;
    }
    // push identity (256 threads: peer = tid>>5, chunk = tid&31)
    float4 *rbuf0 = 0, *rbuf1 = 0;
    int srcidx = 0, dstoff = 0;
    if (tid < 256) {
        const int peer = tid >> 5;
        const int idx = tid & 31, b = idx >> 3, q = idx & 7;
        srcidx = idx;
        dstoff = b * HB_BATCH + (rank * 2 + (q >> 2)) * HB_PITCH + (q & 3);
        rbuf0 = (float4*)cluster.map_shared_rank(&sHbuf[0][0], peer);
        rbuf1 = (float4*)cluster.map_shared_rank(&sHbuf[1][0], peer);
    }

    int par = 0;
    for (int t = 0; t < 512; ++t) {
        // prefetch pre (consumed in phase B)
        float preg = __ldg(pp); pp += pstride;

        // ---- phase A: gate partial dots (fold per batch to cap live regs) ----
        const float4* hb = &sHbuf[par][0];
        float v[4][4];
#pragma unroll
        for (int b = 0; b < 4; ++b) {
            const float4* hp = hb + b * HB_BATCH + ks * HB_PITCH;
            float4 v0 = hp[0], v1 = hp[1], v2 = hp[2], v3 = hp[3];
            unsigned long long h2[8];
            F4TOX2(v0, h2[0], h2[1]);
            F4TOX2(v1, h2[2], h2[3]);
            F4TOX2(v2, h2[4], h2[5]);
            F4TOX2(v3, h2[6], h2[7]);
#pragma unroll
            for (int i = 0; i < 4; ++i) {
                unsigned long long a = 0ULL;
#pragma unroll
                for (int kp = 0; kp < 8; ++kp)
                    FMAX2(a, wr2[i][kp], h2[kp], a);
                float lo, hi;
                UNPX2(lo, hi, a);
                float s = lo + hi;
                s += __shfl_xor_sync(0xffffffffu, s, 1);
                s += __shfl_xor_sync(0xffffffffu, s, 2);
                v[i][b] = s;
            }
        }
        if ((ks & 3) == 0) {
            const int q = ks >> 2;
#pragma unroll
            for (int b = 0; b < 4; ++b)
                ((float4*)sGp)[(q * 4 + b) * (GPF / 4) + rg] =
                    make_float4(v[0][b], v[1][b], v[2][b], v[3][b]);
        }
        __syncthreads();

        // ---- phase B: combine partials + activation (gate-parallel) ----
        {
            float s = sGp[(0 * 4 + pb) * GPF + pr] + sGp[(1 * 4 + pb) * GPF + pr]
                    + sGp[(2 * 4 + pb) * GPF + pr] + sGp[(3 * 4 + pb) * GPF + pr];
            s += preg + sBhh[pr];
            const int type = pr >> 5;
            sAct[pb * GPF + pr] = (type == 2) ? tanh_f(s) : sigm_f(s);
        }
        __syncthreads();

        // ---- phase C: cell update ----
        if (tid < 128) {
            const int cb = tid >> 5, cj = tid & 31;
            const float gi = sAct[cb * GPF + cj];
            const float gf = sAct[cb * GPF + 32 + cj];
            const float gg = sAct[cb * GPF + 64 + cj];
            const float go = sAct[cb * GPF + 96 + cj];
            float c = gf * sC[tid] + gi * gg;
            sC[tid] = c;
            const float h = go * tanh_f(c);
            sStage[cb * 32 + cj] = h;
            *op = h; op += ostride;
        }
        __syncthreads();

        // ---- push h to all peers' next buffer ----
        if (tid < 256) {
            const float4 vsh = ((const float4*)sStage)[srcidx];
            (par ? rbuf0 : rbuf1)[dstoff] = vsh;
        }
        CLUSTER_ARRIVE();
        CLUSTER_WAIT();
        par ^= 1;
    }
}

// ---------------- nop kernel (ncu launch-index steering) ----------------
__global__ void nop_kernel() {}

// ---------------- softmax over 512-wide rows, in place ----------------
__global__ void __launch_bounds__(256) softmax512(float* __restrict__ Sc)
{
    __shared__ float red[256];
    const long base = (long)blockIdx.x * 512;
    const int tid = threadIdx.x;
    float v0 = Sc[base + tid], v1 = Sc[base + tid + 256];
    red[tid] = fmaxf(v0, v1);
    __syncthreads();
    for (int s = 128; s > 0; s >>= 1) {
        if (tid < s) red[tid] = fmaxf(red[tid], red[tid + s]);
        __syncthreads();
    }
    float m = red[0];
    __syncthreads();
    float e0 = expf(v0 - m), e1 = expf(v1 - m);
    red[tid] = e0 + e1;
    __syncthreads();
    for (int s = 128; s > 0; s >>= 1) {
        if (tid < s) red[tid] += red[tid + s];
        __syncthreads();
    }
    float inv = 1.f / red[0];
    Sc[base + tid]       = e0 * inv;
    Sc[base + tid + 256] = e1 * inv;
}

// ---------------- Wv column sum ----------------
__global__ void wvsum_kernel(const float* __restrict__ Wv, const float* __restrict__ bv)
{
    int k = threadIdx.x;
    float s = 0.f;
    for (int j = 0; j < 512; ++j) s += Wv[(long)j * 512 + k];
    g_wvsum[k] = s;
    if (k == 0) {
        float t = 0.f;
        for (int j = 0; j < 512; ++j) t += bv[j];
        g_bvsum[0] = t;
    }
}

// ---------------- intent head (per batch) + intent broadcast ----------------
__global__ void __launch_bounds__(256) intent_kernel(
    const float* __restrict__ out1, const float* __restrict__ Wg, const float* __restrict__ bg,
    const float* __restrict__ Wint, const float* __restrict__ bint,
    float* __restrict__ icl_out, float* __restrict__ int_out)
{
    __shared__ float sq[512], sw[512], sctx[512], siv[64], red[256];
    const int b = blockIdx.x, tid = threadIdx.x;
    const int lane = tid & 31, w = tid >> 5;
    const float* ob = out1 + (long)b * 512 * 512;

    sq[tid] = ob[(long)511 * 512 + tid];
    sq[tid + 256] = ob[(long)511 * 512 + tid + 256];
    __syncthreads();

    for (int s = w; s < 512; s += 8) {
        float sum = 0.f;
        for (int k = lane; k < 512; k += 32) sum += sq[k] * ob[(long)s * 512 + k];
#pragma unroll
        for (int off = 16; off; off >>= 1) sum += __shfl_xor_sync(0xffffffffu, sum, off);
        if (lane == 0) sw[s] = sum;
    }
    __syncthreads();

    float v0 = sw[tid], v1 = sw[tid + 256];
    red[tid] = fmaxf(v0, v1);
    __syncthreads();
    for (int s = 128; s > 0; s >>= 1) { if (tid < s) red[tid] = fmaxf(red[tid], red[tid + s]); __syncthreads(); }
    float m = red[0];
    __syncthreads();
    float e0 = expf(v0 - m), e1 = expf(v1 - m);
    red[tid] = e0 + e1;
    __syncthreads();
    for (int s = 128; s > 0; s >>= 1) { if (tid < s) red[tid] += red[tid + s]; __syncthreads(); }
    float inv = 1.f / red[0];
    sw[tid] = e0 * inv; sw[tid + 256] = e1 * inv;
    __syncthreads();

    float c0 = 0.f, c1 = 0.f;
    for (int s = 0; s < 512; ++s) {
        float wv = sw[s];
        c0 += wv * ob[(long)s * 512 + tid];
        c1 += wv * ob[(long)s * 512 + tid + 256];
    }
    sctx[tid] = c0; sctx[tid + 256] = c1;
    __syncthreads();

    for (int j = w; j < 512; j += 8) {
        float sum = 0.f;
        for (int k = lane; k < 512; k += 32) sum += Wg[(long)j * 512 + k] * sctx[k];
#pragma unroll
        for (int off = 16; off; off >>= 1) sum += __shfl_xor_sync(0xffffffffu, sum, off);
        if (lane == 0) icl_out[b * 512 + j] = sum + bg[j];
    }
    for (int j = w; j < 64; j += 8) {
        float sum = 0.f;
        for (int k = lane; k < 512; k += 32) sum += Wint[(long)j * 512 + k] * (sctx[k] + sq[k]);
#pragma unroll
        for (int off = 16; off; off >>= 1) sum += __shfl_xor_sync(0xffffffffu, sum, off);
        if (lane == 0) siv[j] = sum + bint[j];
    }
    __syncthreads();

    for (int i = tid; i < 512 * 64; i += 256) {
        int t = i >> 6, j = i & 63;
        int_out[((long)b * 512 + t) * 64 + j] = siv[j];
    }
}

// ---------------- gate + build A_tmp = gate*slot_ctx + out1 ----------------
__global__ void __launch_bounds__(256) gate_kernel(
    const float* __restrict__ ctx, const float* __restrict__ icl,
    const float* __restrict__ out1, float* __restrict__ Atmp)
{
    const int w = threadIdx.x >> 5, lane = threadIdx.x & 31;
    const long row = (long)blockIdx.x * 8 + w;
    const int b = (int)(row >> 9);
    const float* cr = ctx + row * 512;
    const float* ir = icl + (long)b * 512;
    float sum = 0.f;
    for (int k = lane; k < 512; k += 32)
        sum += tanhf(cr[k] + ir[k]) * g_wvsum[k];
#pragma unroll
    for (int off = 16; off; off >>= 1) sum += __shfl_xor_sync(0xffffffffu, sum, off);
    float gate = sum + g_bvsum[0];
    const float* orow = out1 + row * 512;
    float* arow = Atmp + row * 512;
    for (int k = lane; k < 512; k += 32)
        arow[k] = gate * cr[k] + orow[k];
}

// ---------------- host launcher ----------------
extern "C" void kernel_launch(void* const* d_in, const int* in_sizes, int n_in,
                              void* d_out, int out_size)
{
    const int*   src   = (const int*)  d_in[0];
    const float* emb   = (const float*)d_in[2];
    const float* Wih   = (const float*)d_in[3];
    const float* Whh   = (const float*)d_in[4];
    const float* bih   = (const float*)d_in[5];
    const float* bhh   = (const float*)d_in[6];
    const float* Wg    = (const float*)d_in[7];
    const float* bg    = (const float*)d_in[8];
    const float* Wv    = (const float*)d_in[9];
    const float* bv    = (const float*)d_in[10];
    const float* Wslot = (const float*)d_in[11];
    const float* bslot = (const float*)d_in[12];
    const float* Wint  = (const float*)d_in[13];
    const float* bint  = (const float*)d_in[14];

    float* out       = (float*)d_out;
    float* slot_out  = out;                      // (B,S,128)
    float* int_out   = out + (size_t)MM * NSLOT; // (B,S,64)

    float *p_pre = 0, *p_out0 = 0, *p_out1 = 0, *p_scores = 0, *p_slotctx = 0, *p_icl = 0;
    (void)cudaGetSymbolAddress((void**)&p_pre,     g_pre);
    (void)cudaGetSymbolAddress((void**)&p_out0,    g_out0);
    (void)cudaGetSymbolAddress((void**)&p_out1,    g_out1);
    (void)cudaGetSymbolAddress((void**)&p_scores,  g_scores);
    (void)cudaGetSymbolAddress((void**)&p_slotctx, g_slotctx);
    (void)cudaGetSymbolAddress((void**)&p_icl,     g_icl);

    // launch 0: wv colsum
    wvsum_kernel<<<1, 512>>>(Wv, bv);

    // launch 1: layer-0 input projection (embedding gather fused)
    {
        dim3 grid(2048 / 128, MM / 128, 1);
        gemm_kernel<true, true><<<grid, 256>>>(nullptr, Wih, bih, p_pre,
                                               MM, 2048, EE, 0, 0, 0, src, emb);
    }
    // launch 2: nop (steers ncu capture onto the next launch)
    nop_kernel<<<1, 32>>>();

    // launch 3: layer-0 recurrence  <- ncu capture target
    lstm_kernel<<<128, 512>>>(p_pre, Whh, bhh, p_out0);

    // layer-1 input projection
    {
        dim3 grid(2048 / 128, MM / 128, 1);
        gemm_kernel<true, false><<<grid, 256>>>(p_out0, Wih + (size_t)2048 * 512,
                                                bih + 2048, p_pre,
                                                MM, 2048, H2, 0, 0, 0, nullptr, nullptr);
    }
    // layer-1 recurrence
    lstm_kernel<<<128, 512>>>(p_pre, Whh + (size_t)2 * H4 * HH,
                              bhh + 2048, p_out1);

    // attention scores: per-batch out @ out^T
    {
        dim3 grid(512 / 128, 512 / 128, BB);
        gemm_kernel<true, false><<<grid, 256>>>(p_out1, p_out1, nullptr, p_scores,
                                                512, 512, 512,
                                                (long)512 * 512, (long)512 * 512, (long)512 * 512,
                                                nullptr, nullptr);
    }
    softmax512<<<MM, 256>>>(p_scores);

    // slot_ctx = w @ out
    {
        dim3 grid(512 / 128, 512 / 128, BB);
        gemm_kernel<false, false><<<grid, 256>>>(p_scores, p_out1, nullptr, p_slotctx,
                                                 512, 512, 512,
                                                 (long)512 * 512, (long)512 * 512, (long)512 * 512,
                                                 nullptr, nullptr);
    }
    intent_kernel<<<BB, 256>>>(p_out1, Wg, bg, Wint, bint, p_icl, int_out);

    gate_kernel<<<MM / 8, 256>>>(p_slotctx, p_icl, p_out1, p_scores);

    // slot_outputs = A_tmp @ Wslot^T + bslot
    {
        dim3 grid(NSLOT / 128, MM / 128, 1);
        gemm_kernel<true, false><<<grid, 256>>>(p_scores, Wslot, bslot, slot_out,
                                                MM, NSLOT, H2, 0, 0, 0, nullptr, nullptr);
    }
}

// round 8
// speedup vs baseline: 1.9887x; 1.2568x over previous
#include <cuda_runtime.h>
#include <cooperative_groups.h>
#include <cstdint>
#include <math.h>

namespace cg = cooperative_groups;

// ---------------- Problem constants ----------------
#define BB    32
#define SS    512
#define EE    512
#define HH    256
#define H4    1024
#define H2    512
#define MM    (BB*SS)      // 16384
#define NSLOT 128
#define NINT  64

// ---------------- Scratch (device globals; no allocation allowed) ----------------
__device__ float g_pre[(size_t)MM*2048];
__device__ float g_out0[(size_t)MM*H2];     // layer-0 out; later reused as out1^T
__device__ float g_out1[(size_t)MM*H2];
__device__ float g_scores[(size_t)MM*H2];   // scores; later reused as A_tmp
__device__ float g_slotctx[(size_t)MM*H2];
__device__ float g_icl[BB*H2];
__device__ float g_wvsum[H2];
__device__ float g_bvsum[1];

// ---------------- packed f32x2 helpers (LSTM) ----------------
#define FMAX2(d, a, b, c) \
    asm("fma.rn.f32x2 %0, %1, %2, %3;" : "=l"(d) : "l"(a), "l"(b), "l"(c))
#define F4TOX2(v, a, b) \
    asm("mov.b64 %0, {%2, %3};\n\tmov.b64 %1, {%4, %5};" \
        : "=l"(a), "=l"(b) : "f"((v).x), "f"((v).y), "f"((v).z), "f"((v).w))
#define UNPX2(lo, hi, v) \
    asm("mov.b64 {%0, %1}, %2;" : "=f"(lo), "=f"(hi) : "l"(v))

#define CLUSTER_ARRIVE() asm volatile("barrier.cluster.arrive.aligned;" ::: "memory")
#define CLUSTER_WAIT()   asm volatile("barrier.cluster.wait.aligned;"   ::: "memory")

__device__ __forceinline__ float sigm_f(float x) {
    return __fdividef(1.f, 1.f + __expf(-x));
}
__device__ __forceinline__ float tanh_f(float x) {
    return __fdividef(2.f, 1.f + __expf(-2.f * x)) - 1.f;
}

// ---------------- mma.sync helpers (sm_80+ baseline; OK on sm_100 base target) ----------------
__device__ __forceinline__ uint32_t smem_u32(const void* p) {
    uint32_t a;
    asm("{ .reg .u64 t; cvta.to.shared.u64 t, %1; cvt.u32.u64 %0, t; }" : "=r"(a) : "l"(p));
    return a;
}
#define LDSM4(r, addr) \
    asm volatile("ldmatrix.sync.aligned.m8n8.x4.shared.b16 {%0,%1,%2,%3}, [%4];" \
                 : "=r"((r)[0]), "=r"((r)[1]), "=r"((r)[2]), "=r"((r)[3]) : "r"(addr))
#define LDSM2(r, addr) \
    asm volatile("ldmatrix.sync.aligned.m8n8.x2.shared.b16 {%0,%1}, [%2];" \
                 : "=r"((r)[0]), "=r"((r)[1]) : "r"(addr))
#define MMA16816(c, a, b) \
    asm volatile("mma.sync.aligned.m16n8k16.row.col.f32.bf16.bf16.f32 " \
                 "{%0,%1,%2,%3}, {%4,%5,%6,%7}, {%8,%9}, {%0,%1,%2,%3};" \
                 : "+f"((c)[0]), "+f"((c)[1]), "+f"((c)[2]), "+f"((c)[3]) \
                 : "r"((a)[0]), "r"((a)[1]), "r"((a)[2]), "r"((a)[3]), \
                   "r"((b)[0]), "r"((b)[1]))

// bf16 split: hi = truncate-to-bf16(f), lo = rn-bf16(f - hi); packed bf16x2 per u32
__device__ __forceinline__ void split8(float4 x0, float4 x1, uint32_t* hi, uint32_t* lo) {
    float f[8] = {x0.x, x0.y, x0.z, x0.w, x1.x, x1.y, x1.z, x1.w};
#pragma unroll
    for (int p = 0; p < 4; ++p) {
        uint32_t u0 = __float_as_uint(f[2*p])   & 0xFFFF0000u;
        uint32_t u1 = __float_as_uint(f[2*p+1]) & 0xFFFF0000u;
        hi[p] = (u0 >> 16) | u1;
        float r0 = f[2*p]   - __uint_as_float(u0);
        float r1 = f[2*p+1] - __uint_as_float(u1);
        asm("cvt.rn.bf16x2.f32 %0, %1, %2;" : "=r"(lo[p]) : "f"(r1), "f"(r0));
    }
}

__device__ __forceinline__ uint32_t sw128(uint32_t off) {
    return off ^ ((off >> 3) & 0x70);
}

// ---------------- split-bf16 HMMA GEMM: C = A @ B^T + bias ----------------
// A: M x K fp32 (opt. gathered rows), B: N x K fp32. K%64==0, M,N%128==0.
// 128x128 tile/CTA, 8 warps (2m x 4n), warp tile 64x32, fp32 accum,
// 3 products per k-chunk: AhBh + AhBl + AlBh.
#define TCG_TILEB     16384                    // one bf16 tile 128x64
#define TCG_OFF_AH    0
#define TCG_OFF_AL    16384
#define TCG_OFF_BH    32768
#define TCG_OFF_BL    49152
#define TCG_STAGE     65536
#define TCG_SMEM      (2*TCG_STAGE)            // 131072

template<bool GATHER>
__global__ void __launch_bounds__(256) tc_gemm(
    const float* __restrict__ A, const float* __restrict__ Bm,
    const float* __restrict__ bias, float* __restrict__ C,
    int M, int N, int K,
    long sA, long sB, long sC,
    const int* __restrict__ gidx, const float* __restrict__ gtab)
{
    extern __shared__ char smem[];
    const uint32_t sbase = smem_u32(smem);
    const int tid = threadIdx.x;
    const int wid = tid >> 5, lane = tid & 31;
    const int wm = wid >> 2, wn = wid & 3;      // warp grid 2 x 4
    const int nbase = blockIdx.x * 128;
    const int mbase = blockIdx.y * 128;

    const float* Ab = GATHER ? gtab : (A + blockIdx.z * sA);
    const float* Bb = Bm + blockIdx.z * sB;
    float*       Cb = C  + blockIdx.z * sC;

    // per-thread load slots: 4 x (row = g>>3, kg = g&7)
    int rowv[4]; long aoffv[4];
#pragma unroll
    for (int i = 0; i < 4; ++i) {
        const int g = tid + i * 256;
        rowv[i] = g >> 3;
        aoffv[i] = GATHER ? (long)gidx[mbase + rowv[i]] * K
                          : (long)(mbase + rowv[i]) * K;
    }
    const int kgq = (tid & 7) * 8;              // k offset (floats) within chunk

    float4 rA[4][2], rB[4][2];
    auto ldg_chunk = [&](int kc) {
#pragma unroll
        for (int i = 0; i < 4; ++i) {
            const float4* ap = (const float4*)(Ab + aoffv[i] + kc + kgq);
            rA[i][0] = ap[0]; rA[i][1] = ap[1];
            const float4* bp = (const float4*)(Bb + (long)(nbase + rowv[i]) * K + kc + kgq);
            rB[i][0] = bp[0]; rB[i][1] = bp[1];
        }
    };
    auto sts_chunk = [&](int stg) {
        char* db = smem + stg * TCG_STAGE;
#pragma unroll
        for (int i = 0; i < 4; ++i) {
            const uint32_t off = sw128((uint32_t)(rowv[i] * 128 + (tid & 7) * 16));
            uint32_t hi[4], lo[4];
            split8(rA[i][0], rA[i][1], hi, lo);
            *(uint4*)(db + TCG_OFF_AH + off) = make_uint4(hi[0], hi[1], hi[2], hi[3]);
            *(uint4*)(db + TCG_OFF_AL + off) = make_uint4(lo[0], lo[1], lo[2], lo[3]);
            split8(rB[i][0], rB[i][1], hi, lo);
            *(uint4*)(db + TCG_OFF_BH + off) = make_uint4(hi[0], hi[1], hi[2], hi[3]);
            *(uint4*)(db + TCG_OFF_BL + off) = make_uint4(lo[0], lo[1], lo[2], lo[3]);
        }
    };

    float acc[4][4][4];
#pragma unroll
    for (int mt = 0; mt < 4; ++mt)
#pragma unroll
        for (int nt = 0; nt < 4; ++nt)
#pragma unroll
            for (int q = 0; q < 4; ++q) acc[mt][nt][q] = 0.f;

    // ldmatrix address offsets (within a tile)
    const uint32_t aoffm = sw128((uint32_t)((wm * 64 + (lane & 15)) * 128 + (lane >> 4) * 16));
    const uint32_t boffm = sw128((uint32_t)((wn * 32 + (lane & 7)) * 128 + ((lane >> 3) & 1) * 16));

    ldg_chunk(0);
    const int NC = K >> 6;
    for (int c = 0; c < NC; ++c) {
        const int s = c & 1;
        sts_chunk(s);
        __syncthreads();
        if (c + 1 < NC) ldg_chunk((c + 1) << 6);

        const uint32_t bAh = sbase + s * TCG_STAGE + TCG_OFF_AH;
        const uint32_t bAl = sbase + s * TCG_STAGE + TCG_OFF_AL;
        const uint32_t bBh = sbase + s * TCG_STAGE + TCG_OFF_BH;
        const uint32_t bBl = sbase + s * TCG_STAGE + TCG_OFF_BL;
#pragma unroll
        for (int kb = 0; kb < 4; ++kb) {
            // XORing the 32-byte k-step into the swizzled offset is valid because
            // sw128 only mixes bits [9:7] into [6:4]; bit5 (32B) is untouched by the mix.
            const uint32_t kx = kb * 32;
            uint32_t ah[4][4], al[4][4];
#pragma unroll
            for (int mt = 0; mt < 4; ++mt) {
                const uint32_t o = (aoffm + mt * 16 * 128) ^ kx;
                LDSM4(ah[mt], bAh + o);
                LDSM4(al[mt], bAl + o);
            }
            uint32_t bh[4][2], bl[4][2];
#pragma unroll
            for (int nt = 0; nt < 4; ++nt) {
                const uint32_t o = (boffm + nt * 8 * 128) ^ kx;
                LDSM2(bh[nt], bBh + o);
                LDSM2(bl[nt], bBl + o);
            }
#pragma unroll
            for (int mt = 0; mt < 4; ++mt)
#pragma unroll
                for (int nt = 0; nt < 4; ++nt) {
                    MMA16816(acc[mt][nt], ah[mt], bh[nt]);
                    MMA16816(acc[mt][nt], ah[mt], bl[nt]);
                    MMA16816(acc[mt][nt], al[mt], bh[nt]);
                }
        }
        __syncthreads();
    }

    // epilogue
#pragma unroll
    for (int mt = 0; mt < 4; ++mt) {
        const int row = mbase + wm * 64 + mt * 16 + (lane >> 2);
#pragma unroll
        for (int nt = 0; nt < 4; ++nt) {
            const int col = nbase + wn * 32 + nt * 8 + (lane & 3) * 2;
            const float b0 = bias ? bias[col] : 0.f;
            const float b1 = bias ? bias[col + 1] : 0.f;
            float2 v0 = make_float2(acc[mt][nt][0] + b0, acc[mt][nt][1] + b1);
            float2 v1 = make_float2(acc[mt][nt][2] + b0, acc[mt][nt][3] + b1);
            *(float2*)(Cb + (long)row * N + col)       = v0;
            *(float2*)(Cb + (long)(row + 8) * N + col) = v1;
        }
    }
}

// ---------------- batched 512x512 transpose: outT[b][d][s] = in[b][s][d] ----------------
__global__ void __launch_bounds__(256) transpose512(
    const float* __restrict__ in, float* __restrict__ outT)
{
    __shared__ float t[32][33];
    const int b = blockIdx.z;
    const int s0 = blockIdx.x * 32, d0 = blockIdx.y * 32;
    const float* ib = in  + (long)b * 512 * 512;
    float*       ob = outT + (long)b * 512 * 512;
    const int x = threadIdx.x & 31, y = threadIdx.x >> 5;
#pragma unroll
    for (int i = y; i < 32; i += 8)
        t[i][x] = ib[(long)(s0 + i) * 512 + d0 + x];
    __syncthreads();
#pragma unroll
    for (int i = y; i < 32; i += 8)
        ob[(long)(d0 + i) * 512 + s0 + x] = t[x][i];
}

// ---------------- BiLSTM recurrence (v3b) ----------------
#define HB_PITCH 5
#define HB_BATCH (16*HB_PITCH)
#define HB_TOT   (4*HB_BATCH)
#define GPF      132

__global__ void __cluster_dims__(8, 1, 1) __launch_bounds__(512, 1)
lstm_kernel(const float* __restrict__ pre, const float* __restrict__ Whh,
            const float* __restrict__ bhh, float* __restrict__ out)
{
    __shared__ float4 sHbuf[2][HB_TOT];
    __shared__ float  sGp[16*GPF];
    __shared__ float  sAct[4*GPF];
    __shared__ float  sStage[128];
    __shared__ float  sBhh[128];
    __shared__ float  sC[128];

    cg::cluster_group cluster = cg::this_cluster();
    const int rank = cluster.block_rank();
    const int cid  = blockIdx.x >> 3;
    const int dir  = cid & 1;
    const int b0   = (cid >> 1) * 4;
    const int tid  = threadIdx.x;

    const int rg = tid >> 4;
    const int ks = tid & 15;
    const int r0 = rg * 4;
    const int pb = tid >> 7;
    const int pr = tid & 127;
    const int grow_pr = (pr >> 5) * 256 + rank * 32 + (pr & 31);

    unsigned long long wr2[4][8];
    {
        const int type0 = r0 >> 5;
#pragma unroll
        for (int i = 0; i < 4; ++i) {
            const int gr = type0 * 256 + rank * 32 + ((r0 + i) & 31);
            const float4* W4 = (const float4*)(Whh + ((long)(dir * 1024 + gr)) * 256 + ks * 16);
#pragma unroll
            for (int q = 0; q < 4; ++q) {
                float4 w = W4[q];
                F4TOX2(w, wr2[i][q * 2], wr2[i][q * 2 + 1]);
            }
        }
    }
    if (tid < 128) {
        sBhh[tid] = bhh[dir * 1024 + (tid >> 5) * 256 + rank * 32 + (tid & 31)];
        sC[tid] = 0.f;
    }
    {
        float4 z = make_float4(0.f, 0.f, 0.f, 0.f);
        for (int i = tid; i < 2 * HB_TOT; i += 512) ((float4*)sHbuf)[i] = z;
    }
    __syncthreads();
    CLUSTER_ARRIVE(); CLUSTER_WAIT();

    const long pstride = dir ? -2048L : 2048L;
    const float* pp = pre + ((long)((b0 + pb) * 512 + (dir ? 511 : 0))) * 2048
                          + dir * 1024 + grow_pr;
    float* op = out;
    long ostride = 0;
    if (tid < 128) {
        const int cb = tid >> 5, cj = tid & 31;
        op = out + ((long)((b0 + cb) * 512 + (dir ? 511 : 0))) * 512
                 + dir * 256 + rank * 32 + cj;
        ostride = dir ? -512L : 512L;
    }
    float4 *rbuf0 = 0, *rbuf1 = 0;
    int srcidx = 0, dstoff = 0;
    if (tid < 256) {
        const int peer = tid >> 5;
        const int idx = tid & 31, b = idx >> 3, q = idx & 7;
        srcidx = idx;
        dstoff = b * HB_BATCH + (rank * 2 + (q >> 2)) * HB_PITCH + (q & 3);
        rbuf0 = (float4*)cluster.map_shared_rank(&sHbuf[0][0], peer);
        rbuf1 = (float4*)cluster.map_shared_rank(&sHbuf[1][0], peer);
    }

    int par = 0;
    for (int t = 0; t < 512; ++t) {
        float preg = __ldg(pp); pp += pstride;

        const float4* hb = &sHbuf[par][0];
        float v[4][4];
#pragma unroll
        for (int b = 0; b < 4; ++b) {
            const float4* hp = hb + b * HB_BATCH + ks * HB_PITCH;
            float4 v0 = hp[0], v1 = hp[1], v2 = hp[2], v3 = hp[3];
            unsigned long long h2[8];
            F4TOX2(v0, h2[0], h2[1]);
            F4TOX2(v1, h2[2], h2[3]);
            F4TOX2(v2, h2[4], h2[5]);
            F4TOX2(v3, h2[6], h2[7]);
#pragma unroll
            for (int i = 0; i < 4; ++i) {
                unsigned long long a = 0ULL;
#pragma unroll
                for (int kp = 0; kp < 8; ++kp)
                    FMAX2(a, wr2[i][kp], h2[kp], a);
                float lo, hi;
                UNPX2(lo, hi, a);
                float s = lo + hi;
                s += __shfl_xor_sync(0xffffffffu, s, 1);
                s += __shfl_xor_sync(0xffffffffu, s, 2);
                v[i][b] = s;
            }
        }
        if ((ks & 3) == 0) {
            const int q = ks >> 2;
#pragma unroll
            for (int b = 0; b < 4; ++b)
                ((float4*)sGp)[(q * 4 + b) * (GPF / 4) + rg] =
                    make_float4(v[0][b], v[1][b], v[2][b], v[3][b]);
        }
        __syncthreads();

        {
            float s = sGp[(0 * 4 + pb) * GPF + pr] + sGp[(1 * 4 + pb) * GPF + pr]
                    + sGp[(2 * 4 + pb) * GPF + pr] + sGp[(3 * 4 + pb) * GPF + pr];
            s += preg + sBhh[pr];
            const int type = pr >> 5;
            sAct[pb * GPF + pr] = (type == 2) ? tanh_f(s) : sigm_f(s);
        }
        __syncthreads();

        if (tid < 128) {
            const int cb = tid >> 5, cj = tid & 31;
            const float gi = sAct[cb * GPF + cj];
            const float gf = sAct[cb * GPF + 32 + cj];
            const float gg = sAct[cb * GPF + 64 + cj];
            const float go = sAct[cb * GPF + 96 + cj];
            float c = gf * sC[tid] + gi * gg;
            sC[tid] = c;
            const float h = go * tanh_f(c);
            sStage[cb * 32 + cj] = h;
            *op = h; op += ostride;
        }
        __syncthreads();

        if (tid < 256) {
            const float4 vsh = ((const float4*)sStage)[srcidx];
            (par ? rbuf0 : rbuf1)[dstoff] = vsh;
        }
        CLUSTER_ARRIVE();
        CLUSTER_WAIT();
        par ^= 1;
    }
}

// ---------------- softmax over 512-wide rows, in place ----------------
__global__ void __launch_bounds__(256) softmax512(float* __restrict__ Sc)
{
    __shared__ float red[256];
    const long base = (long)blockIdx.x * 512;
    const int tid = threadIdx.x;
    float v0 = Sc[base + tid], v1 = Sc[base + tid + 256];
    red[tid] = fmaxf(v0, v1);
    __syncthreads();
    for (int s = 128; s > 0; s >>= 1) {
        if (tid < s) red[tid] = fmaxf(red[tid], red[tid + s]);
        __syncthreads();
    }
    float m = red[0];
    __syncthreads();
    float e0 = expf(v0 - m), e1 = expf(v1 - m);
    red[tid] = e0 + e1;
    __syncthreads();
    for (int s = 128; s > 0; s >>= 1) {
        if (tid < s) red[tid] += red[tid + s];
        __syncthreads();
    }
    float inv = 1.f / red[0];
    Sc[base + tid]       = e0 * inv;
    Sc[base + tid + 256] = e1 * inv;
}

// ---------------- Wv column sum ----------------
__global__ void wvsum_kernel(const float* __restrict__ Wv, const float* __restrict__ bv)
{
    int k = threadIdx.x;
    float s = 0.f;
    for (int j = 0; j < 512; ++j) s += Wv[(long)j * 512 + k];
    g_wvsum[k] = s;
    if (k == 0) {
        float t = 0.f;
        for (int j = 0; j < 512; ++j) t += bv[j];
        g_bvsum[0] = t;
    }
}

// ---------------- intent head (per batch) + intent broadcast ----------------
__global__ void __launch_bounds__(256) intent_kernel(
    const float* __restrict__ out1, const float* __restrict__ Wg, const float* __restrict__ bg,
    const float* __restrict__ Wint, const float* __restrict__ bint,
    float* __restrict__ icl_out, float* __restrict__ int_out)
{
    __shared__ float sq[512], sw[512], sctx[512], siv[64], red[256];
    const int b = blockIdx.x, tid = threadIdx.x;
    const int lane = tid & 31, w = tid >> 5;
    const float* ob = out1 + (long)b * 512 * 512;

    sq[tid] = ob[(long)511 * 512 + tid];
    sq[tid + 256] = ob[(long)511 * 512 + tid + 256];
    __syncthreads();

    for (int s = w; s < 512; s += 8) {
        float sum = 0.f;
        for (int k = lane; k < 512; k += 32) sum += sq[k] * ob[(long)s * 512 + k];
#pragma unroll
        for (int off = 16; off; off >>= 1) sum += __shfl_xor_sync(0xffffffffu, sum, off);
        if (lane == 0) sw[s] = sum;
    }
    __syncthreads();

    float v0 = sw[tid], v1 = sw[tid + 256];
    red[tid] = fmaxf(v0, v1);
    __syncthreads();
    for (int s = 128; s > 0; s >>= 1) { if (tid < s) red[tid] = fmaxf(red[tid], red[tid + s]); __syncthreads(); }
    float m = red[0];
    __syncthreads();
    float e0 = expf(v0 - m), e1 = expf(v1 - m);
    red[tid] = e0 + e1;
    __syncthreads();
    for (int s = 128; s > 0; s >>= 1) { if (tid < s) red[tid] += red[tid + s]; __syncthreads(); }
    float inv = 1.f / red[0];
    sw[tid] = e0 * inv; sw[tid + 256] = e1 * inv;
    __syncthreads();

    float c0 = 0.f, c1 = 0.f;
    for (int s = 0; s < 512; ++s) {
        float wv = sw[s];
        c0 += wv * ob[(long)s * 512 + tid];
        c1 += wv * ob[(long)s * 512 + tid + 256];
    }
    sctx[tid] = c0; sctx[tid + 256] = c1;
    __syncthreads();

    for (int j = w; j < 512; j += 8) {
        float sum = 0.f;
        for (int k = lane; k < 512; k += 32) sum += Wg[(long)j * 512 + k] * sctx[k];
#pragma unroll
        for (int off = 16; off; off >>= 1) sum += __shfl_xor_sync(0xffffffffu, sum, off);
        if (lane == 0) icl_out[b * 512 + j] = sum + bg[j];
    }
    for (int j = w; j < 64; j += 8) {
        float sum = 0.f;
        for (int k = lane; k < 512; k += 32) sum += Wint[(long)j * 512 + k] * (sctx[k] + sq[k]);
#pragma unroll
        for (int off = 16; off; off >>= 1) sum += __shfl_xor_sync(0xffffffffu, sum, off);
        if (lane == 0) siv[j] = sum + bint[j];
    }
    __syncthreads();

    for (int i = tid; i < 512 * 64; i += 256) {
        int t = i >> 6, j = i & 63;
        int_out[((long)b * 512 + t) * 64 + j] = siv[j];
    }
}

// ---------------- gate + build A_tmp = gate*slot_ctx + out1 ----------------
__global__ void __launch_bounds__(256) gate_kernel(
    const float* __restrict__ ctx, const float* __restrict__ icl,
    const float* __restrict__ out1, float* __restrict__ Atmp)
{
    const int w = threadIdx.x >> 5, lane = threadIdx.x & 31;
    const long row = (long)blockIdx.x * 8 + w;
    const int b = (int)(row >> 9);
    const float* cr = ctx + row * 512;
    const float* ir = icl + (long)b * 512;
    float sum = 0.f;
    for (int k = lane; k < 512; k += 32)
        sum += tanhf(cr[k] + ir[k]) * g_wvsum[k];
#pragma unroll
    for (int off = 16; off; off >>= 1) sum += __shfl_xor_sync(0xffffffffu, sum, off);
    float gate = sum + g_bvsum[0];
    const float* orow = out1 + row * 512;
    float* arow = Atmp + row * 512;
    for (int k = lane; k < 512; k += 32)
        arow[k] = gate * cr[k] + orow[k];
}

// ---------------- host launcher ----------------
extern "C" void kernel_launch(void* const* d_in, const int* in_sizes, int n_in,
                              void* d_out, int out_size)
{
    const int*   src   = (const int*)  d_in[0];
    const float* emb   = (const float*)d_in[2];
    const float* Wih   = (const float*)d_in[3];
    const float* Whh   = (const float*)d_in[4];
    const float* bih   = (const float*)d_in[5];
    const float* bhh   = (const float*)d_in[6];
    const float* Wg    = (const float*)d_in[7];
    const float* bg    = (const float*)d_in[8];
    const float* Wv    = (const float*)d_in[9];
    const float* bv    = (const float*)d_in[10];
    const float* Wslot = (const float*)d_in[11];
    const float* bslot = (const float*)d_in[12];
    const float* Wint  = (const float*)d_in[13];
    const float* bint  = (const float*)d_in[14];

    float* out       = (float*)d_out;
    float* slot_out  = out;
    float* int_out   = out + (size_t)MM * NSLOT;

    float *p_pre = 0, *p_out0 = 0, *p_out1 = 0, *p_scores = 0, *p_slotctx = 0, *p_icl = 0;
    (void)cudaGetSymbolAddress((void**)&p_pre,     g_pre);
    (void)cudaGetSymbolAddress((void**)&p_out0,    g_out0);
    (void)cudaGetSymbolAddress((void**)&p_out1,    g_out1);
    (void)cudaGetSymbolAddress((void**)&p_scores,  g_scores);
    (void)cudaGetSymbolAddress((void**)&p_slotctx, g_slotctx);
    (void)cudaGetSymbolAddress((void**)&p_icl,     g_icl);

    (void)cudaFuncSetAttribute((const void*)tc_gemm<true>,
                               cudaFuncAttributeMaxDynamicSharedMemorySize, TCG_SMEM);
    (void)cudaFuncSetAttribute((const void*)tc_gemm<false>,
                               cudaFuncAttributeMaxDynamicSharedMemorySize, TCG_SMEM);

    // 0: wv colsum
    wvsum_kernel<<<1, 512>>>(Wv, bv);

    // 1: layer-0 input projection (embedding gather fused)
    {
        dim3 grid(2048 / 128, MM / 128, 1);
        tc_gemm<true><<<grid, 256, TCG_SMEM>>>(nullptr, Wih, bih, p_pre,
                                               MM, 2048, EE, 0, 0, 0, src, emb);
    }
    // 2: layer-0 recurrence
    lstm_kernel<<<128, 512>>>(p_pre, Whh, bhh, p_out0);

    // 3: layer-1 input projection
    {
        dim3 grid(2048 / 128, MM / 128, 1);
        tc_gemm<false><<<grid, 256, TCG_SMEM>>>(p_out0, Wih + (size_t)2048 * 512,
                                                bih + 2048, p_pre,
                                                MM, 2048, H2, 0, 0, 0, nullptr, nullptr);
    }
    // 4: layer-1 recurrence
    lstm_kernel<<<128, 512>>>(p_pre, Whh + (size_t)2 * H4 * HH,
                              bhh + 2048, p_out1);

    // 5: attention scores (ncu capture target): per-batch out @ out^T
    {
        dim3 grid(512 / 128, 512 / 128, BB);
        tc_gemm<false><<<grid, 256, TCG_SMEM>>>(p_out1, p_out1, nullptr, p_scores,
                                                512, 512, 512,
                                                (long)512 * 512, (long)512 * 512, (long)512 * 512,
                                                nullptr, nullptr);
    }
    softmax512<<<MM, 256>>>(p_scores);

    // transpose out1 -> g_out0 (per batch): outT[d][s]
    {
        dim3 grid(16, 16, BB);
        transpose512<<<grid, 256>>>(p_out1, p_out0);
    }
    // slot_ctx = w @ out  (B = outT, K-major)
    {
        dim3 grid(512 / 128, 512 / 128, BB);
        tc_gemm<false><<<grid, 256, TCG_SMEM>>>(p_scores, p_out0, nullptr, p_slotctx,
                                                512, 512, 512,
                                                (long)512 * 512, (long)512 * 512, (long)512 * 512,
                                                nullptr, nullptr);
    }
    intent_kernel<<<BB, 256>>>(p_out1, Wg, bg, Wint, bint, p_icl, int_out);

    gate_kernel<<<MM / 8, 256>>>(p_slotctx, p_icl, p_out1, p_scores);

    // slot_outputs = A_tmp @ Wslot^T + bslot
    {
        dim3 grid(NSLOT / 128, MM / 128, 1);
        tc_gemm<false><<<grid, 256, TCG_SMEM>>>(p_scores, Wslot, bslot, slot_out,
                                                MM, NSLOT, H2, 0, 0, 0, nullptr, nullptr);
    }
}